// round 12
// baseline (speedup 1.0000x reference)
#include <cuda_runtime.h>

// SVConv2d: out[n,o,h,w] = bias[o] + sum_{ci,kh,kw} x[n,ci,h+kh-1,w+kw-1] * W[o,ci,kh,kw,h,w]
// N=8, Cin=Cout=32, K=3, H=W=64. Weight (151 MB) streams once -> DRAM-bound.
// R12: CPB 2->4 to amortize x L1 wavefronts over 4 couts (L1 was co-binding
// at 58%). 36-weight burst prefetch per cin, double-buffered; 16 warps/SM
// with 36 weight lines in flight each. Atomics epilogue, bias pre-init.

typedef unsigned long long ull;

#define HW 4096
#define PD 66            // padded spatial dim
#define PP (PD * PD)     // 4356
#define SPLIT 2
#define CPB 4

// scratch (allocation-free: __device__ globals)
__device__ float4 g_xp0[32 * PP];              // (cin, 66, 66) n0..3 : 2.2 MB
__device__ float4 g_xp1[32 * PP];              // (cin, 66, 66) n4..7 : 2.2 MB

__device__ __forceinline__ ull pack2(float a, float b) {
    ull r; asm("mov.b64 %0, {%1, %2};" : "=l"(r) : "f"(a), "f"(b)); return r;
}
__device__ __forceinline__ void fma2(ull& d, ull a, ull b) {
    asm("fma.rn.f32x2 %0, %1, %2, %0;" : "+l"(d) : "l"(a), "l"(b));
}
__device__ __forceinline__ float2 unpack2(ull v) {
    float x, y; asm("mov.b64 {%0, %1}, %2;" : "=f"(x), "=f"(y) : "l"(v));
    return make_float2(x, y);
}

// ---- kernel 1a: zero the padded borders (260 cells per cin) ----
__global__ __launch_bounds__(256) void zero_border() {
    int idx = blockIdx.x * 256 + threadIdx.x;      // < 32 * 260
    if (idx >= 32 * 260) return;
    int cin = idx / 260, r = idx - cin * 260;
    int hp, wp;
    if (r < 66)       { hp = 0;            wp = r; }
    else if (r < 132) { hp = 65;           wp = r - 66; }
    else if (r < 196) { hp = r - 132 + 1;  wp = 0; }
    else              { hp = r - 196 + 1;  wp = 65; }
    float4 z = make_float4(0.f, 0.f, 0.f, 0.f);
    g_xp0[cin * PP + hp * PD + wp] = z;
    g_xp1[cin * PP + hp * PD + wp] = z;
}

// ---- kernel 1b: interior transpose, 4 pixels/thread, vector loads/stores ----
__global__ __launch_bounds__(256) void build_xpad(const float* __restrict__ x) {
    int idx = blockIdx.x * 256 + threadIdx.x;      // < 32*64*16 = 32768
    if (idx >= 32 * 64 * 16) return;
    int cin = idx >> 10;
    int rem = idx & 1023;
    int h = rem >> 4;
    int w4 = (rem & 15) * 4;

    float4 v[8];
#pragma unroll
    for (int n = 0; n < 8; n++)
        v[n] = *(const float4*)(x + (size_t)(n * 32 + cin) * HW + h * 64 + w4);

    float4* p0 = g_xp0 + (size_t)cin * PP + (h + 1) * PD + (w4 + 1);
    float4* p1 = g_xp1 + (size_t)cin * PP + (h + 1) * PD + (w4 + 1);
#pragma unroll
    for (int j = 0; j < 4; j++) {
        p0[j] = make_float4(((const float*)&v[0])[j], ((const float*)&v[1])[j],
                            ((const float*)&v[2])[j], ((const float*)&v[3])[j]);
        p1[j] = make_float4(((const float*)&v[4])[j], ((const float*)&v[5])[j],
                            ((const float*)&v[6])[j], ((const float*)&v[7])[j]);
    }
}

// ---- kernel 1c: initialize out with bias ----
__global__ __launch_bounds__(256) void init_out(const float* __restrict__ bias,
                                                float4* __restrict__ out) {
    int idx = blockIdx.x * 256 + threadIdx.x;      // < 8*32*4096/4 = 262144
    float b = __ldg(bias + ((idx >> 10) & 31));
    out[idx] = make_float4(b, b, b, b);
}

// load 36 weights (9 taps x 4 couts) for one cin into registers (one burst)
__device__ __forceinline__ void loadW(float* wb, const float* wp) {
#pragma unroll
    for (int c = 0; c < CPB; c++)
#pragma unroll
        for (int t = 0; t < 9; t++)
            wb[c * 9 + t] = __ldcs(wp + (size_t)c * (32 * 9 * HW) + t * HW);
}

// consume one cin: 18 x-load quads worth of FMAs with registered weights
__device__ __forceinline__ void fmaTaps(const float* wb,
                                        const float4* xb0, const float4* xb1,
                                        ull acc[CPB][4]) {
#pragma unroll
    for (int t = 0; t < 9; t++) {
        const int off = (t / 3 - 1) * PD + (t % 3 - 1);  // compile-time
        float4 lo = __ldg(xb0 + off);
        float4 hi = __ldg(xb1 + off);
        ull xq0 = pack2(lo.x, lo.y);
        ull xq1 = pack2(lo.z, lo.w);
        ull xq2 = pack2(hi.x, hi.y);
        ull xq3 = pack2(hi.z, hi.w);
#pragma unroll
        for (int c = 0; c < CPB; c++) {
            ull wd = pack2(wb[c * 9 + t], wb[c * 9 + t]);
            fma2(acc[c][0], wd, xq0);
            fma2(acc[c][1], wd, xq1);
            fma2(acc[c][2], wd, xq2);
            fma2(acc[c][3], wd, xq3);
        }
    }
}

// ---- kernel 2: main. block (32,4); warp = 32 consecutive w; no smem/barriers ----
__global__ __launch_bounds__(128) void svconv_main(const float* __restrict__ wt_g,
                                                   float* __restrict__ out) {
    const int lane = threadIdx.x, row = threadIdx.y;
    const int px = blockIdx.x * 32 + lane;
    const int py = blockIdx.y * 4 + row;
    const int c0 = (blockIdx.z & 7) * CPB;         // cout group (4 couts)
    const int s = blockIdx.z >> 3;                 // cin half

    ull acc[CPB][4];
#pragma unroll
    for (int c = 0; c < CPB; c++)
#pragma unroll
        for (int j = 0; j < 4; j++) acc[c][j] = 0ull;

    const float4* xb0 = g_xp0 + (size_t)(s * 16) * PP + (py + 1) * PD + (px + 1);
    const float4* xb1 = g_xp1 + (size_t)(s * 16) * PP + (py + 1) * PD + (px + 1);
    const float* wp = wt_g + (size_t)(c0 * 32 + s * 16) * 9 * HW + py * 64 + px;

    float wA[36], wB[36];
    loadW(wA, wp);                                  // cin 0

#pragma unroll 1
    for (int ci = 0; ci < 16; ci += 2) {
        // prefetch cin+1 (burst), then consume cin
        loadW(wB, wp + (size_t)9 * HW);
        fmaTaps(wA, xb0, xb1, acc);
        xb0 += PP; xb1 += PP;

        // prefetch cin+2 (burst, clamped in-bounds on last), then consume cin+1
        const float* p2 = wp + (size_t)(ci + 2 < 16 ? 2 : 0) * 9 * HW;
        loadW(wA, p2);
        fmaTaps(wB, xb0, xb1, acc);
        xb0 += PP; xb1 += PP;

        wp += (size_t)18 * HW;                     // advance 2 cins
    }

    // ---- epilogue: atomic accumulate into out (bias pre-added by init_out) ----
    float* ob = out + (size_t)c0 * HW + py * 64 + px;
#pragma unroll
    for (int c = 0; c < CPB; c++)
#pragma unroll
        for (int j = 0; j < 4; j++) {
            float2 v = unpack2(acc[c][j]);
            int n0 = 2 * j, n1 = 2 * j + 1;
            atomicAdd(ob + (((size_t)n0 * 32) + c) * HW, v.x);
            atomicAdd(ob + (((size_t)n1 * 32) + c) * HW, v.y);
        }
}

extern "C" void kernel_launch(void* const* d_in, const int* in_sizes, int n_in,
                              void* d_out, int out_size) {
    const float* x = (const float*)d_in[0];
    const float* wgt = (const float*)d_in[1];
    const float* bias = (const float*)d_in[2];
    float* out = (float*)d_out;

    zero_border<<<(32 * 260 + 255) / 256, 256>>>();
    build_xpad<<<(32 * 64 * 16 + 255) / 256, 256>>>(x);
    init_out<<<(8 * 32 * HW / 4) / 256, 256>>>(bias, (float4*)out);
    dim3 grid(2, 16, 8 * SPLIT);                   // 2 x 16 x 16 = 512 blocks
    dim3 block(32, 4);                             // 128 threads
    svconv_main<<<grid, block>>>(wgt, out);
}

// round 13
// speedup vs baseline: 1.0156x; 1.0156x over previous
#include <cuda_runtime.h>

// SVConv2d: out[n,o,h,w] = bias[o] + sum_{ci,kh,kw} x[n,ci,h+kh-1,w+kw-1] * W[o,ci,kh,kw,h,w]
// N=8, Cin=Cout=32, K=3, H=W=64. Weight (151 MB) streams once -> DRAM-bound.
// R13: CPB=4 (L1-amortized, from R12) + SPLIT=4 -> 1024 half-size blocks so
// all SMs stay at the 4-CTA register limit with a smooth tail. zero_border
// and init_out merged into one prep kernel. Atomics epilogue.

typedef unsigned long long ull;

#define HW 4096
#define PD 66            // padded spatial dim
#define PP (PD * PD)     // 4356
#define SPLIT 4
#define CPB 4
#define CINS (32 / SPLIT)   // 8 cins per block

// scratch (allocation-free: __device__ globals)
__device__ float4 g_xp0[32 * PP];              // (cin, 66, 66) n0..3 : 2.2 MB
__device__ float4 g_xp1[32 * PP];              // (cin, 66, 66) n4..7 : 2.2 MB

__device__ __forceinline__ ull pack2(float a, float b) {
    ull r; asm("mov.b64 %0, {%1, %2};" : "=l"(r) : "f"(a), "f"(b)); return r;
}
__device__ __forceinline__ void fma2(ull& d, ull a, ull b) {
    asm("fma.rn.f32x2 %0, %1, %2, %0;" : "+l"(d) : "l"(a), "l"(b));
}
__device__ __forceinline__ float2 unpack2(ull v) {
    float x, y; asm("mov.b64 {%0, %1}, %2;" : "=f"(x), "=f"(y) : "l"(v));
    return make_float2(x, y);
}

// ---- kernel 1a: prep = init out with bias + zero padded borders ----
__global__ __launch_bounds__(256) void prep(const float* __restrict__ bias,
                                            float4* __restrict__ out) {
    int idx = blockIdx.x * 256 + threadIdx.x;      // < 8*32*4096/4 = 262144
    float b = __ldg(bias + ((idx >> 10) & 31));
    out[idx] = make_float4(b, b, b, b);

    if (idx < 32 * 260) {                          // border cells (260 per cin)
        int cin = idx / 260, r = idx - cin * 260;
        int hp, wp;
        if (r < 66)       { hp = 0;            wp = r; }
        else if (r < 132) { hp = 65;           wp = r - 66; }
        else if (r < 196) { hp = r - 132 + 1;  wp = 0; }
        else              { hp = r - 196 + 1;  wp = 65; }
        float4 z = make_float4(0.f, 0.f, 0.f, 0.f);
        g_xp0[cin * PP + hp * PD + wp] = z;
        g_xp1[cin * PP + hp * PD + wp] = z;
    }
}

// ---- kernel 1b: interior transpose, 4 pixels/thread, vector loads/stores ----
__global__ __launch_bounds__(256) void build_xpad(const float* __restrict__ x) {
    int idx = blockIdx.x * 256 + threadIdx.x;      // < 32*64*16 = 32768
    if (idx >= 32 * 64 * 16) return;
    int cin = idx >> 10;
    int rem = idx & 1023;
    int h = rem >> 4;
    int w4 = (rem & 15) * 4;

    float4 v[8];
#pragma unroll
    for (int n = 0; n < 8; n++)
        v[n] = *(const float4*)(x + (size_t)(n * 32 + cin) * HW + h * 64 + w4);

    float4* p0 = g_xp0 + (size_t)cin * PP + (h + 1) * PD + (w4 + 1);
    float4* p1 = g_xp1 + (size_t)cin * PP + (h + 1) * PD + (w4 + 1);
#pragma unroll
    for (int j = 0; j < 4; j++) {
        p0[j] = make_float4(((const float*)&v[0])[j], ((const float*)&v[1])[j],
                            ((const float*)&v[2])[j], ((const float*)&v[3])[j]);
        p1[j] = make_float4(((const float*)&v[4])[j], ((const float*)&v[5])[j],
                            ((const float*)&v[6])[j], ((const float*)&v[7])[j]);
    }
}

// load 36 weights (9 taps x 4 couts) for one cin into registers (one burst)
__device__ __forceinline__ void loadW(float* wb, const float* wp) {
#pragma unroll
    for (int c = 0; c < CPB; c++)
#pragma unroll
        for (int t = 0; t < 9; t++)
            wb[c * 9 + t] = __ldcs(wp + (size_t)c * (32 * 9 * HW) + t * HW);
}

// consume one cin: 18 x-load quads worth of FMAs with registered weights
__device__ __forceinline__ void fmaTaps(const float* wb,
                                        const float4* xb0, const float4* xb1,
                                        ull acc[CPB][4]) {
#pragma unroll
    for (int t = 0; t < 9; t++) {
        const int off = (t / 3 - 1) * PD + (t % 3 - 1);  // compile-time
        float4 lo = __ldg(xb0 + off);
        float4 hi = __ldg(xb1 + off);
        ull xq0 = pack2(lo.x, lo.y);
        ull xq1 = pack2(lo.z, lo.w);
        ull xq2 = pack2(hi.x, hi.y);
        ull xq3 = pack2(hi.z, hi.w);
#pragma unroll
        for (int c = 0; c < CPB; c++) {
            ull wd = pack2(wb[c * 9 + t], wb[c * 9 + t]);
            fma2(acc[c][0], wd, xq0);
            fma2(acc[c][1], wd, xq1);
            fma2(acc[c][2], wd, xq2);
            fma2(acc[c][3], wd, xq3);
        }
    }
}

// ---- kernel 2: main. block (32,4); warp = 32 consecutive w; no smem/barriers ----
__global__ __launch_bounds__(128) void svconv_main(const float* __restrict__ wt_g,
                                                   float* __restrict__ out) {
    const int lane = threadIdx.x, row = threadIdx.y;
    const int px = blockIdx.x * 32 + lane;
    const int py = blockIdx.y * 4 + row;
    const int c0 = (blockIdx.z & 7) * CPB;         // cout group (4 couts)
    const int s = blockIdx.z >> 3;                 // cin quarter

    ull acc[CPB][4];
#pragma unroll
    for (int c = 0; c < CPB; c++)
#pragma unroll
        for (int j = 0; j < 4; j++) acc[c][j] = 0ull;

    const float4* xb0 = g_xp0 + (size_t)(s * CINS) * PP + (py + 1) * PD + (px + 1);
    const float4* xb1 = g_xp1 + (size_t)(s * CINS) * PP + (py + 1) * PD + (px + 1);
    const float* wp = wt_g + (size_t)(c0 * 32 + s * CINS) * 9 * HW + py * 64 + px;

    float wA[36], wB[36];
    loadW(wA, wp);                                  // first cin

#pragma unroll 1
    for (int ci = 0; ci < CINS; ci += 2) {
        // prefetch cin+1 (burst), then consume cin
        loadW(wB, wp + (size_t)9 * HW);
        fmaTaps(wA, xb0, xb1, acc);
        xb0 += PP; xb1 += PP;

        // prefetch cin+2 (burst, clamped in-bounds on last), then consume cin+1
        const float* p2 = wp + (size_t)(ci + 2 < CINS ? 2 : 0) * 9 * HW;
        loadW(wA, p2);
        fmaTaps(wB, xb0, xb1, acc);
        xb0 += PP; xb1 += PP;

        wp += (size_t)18 * HW;                     // advance 2 cins
    }

    // ---- epilogue: atomic accumulate into out (bias pre-added by prep) ----
    float* ob = out + (size_t)c0 * HW + py * 64 + px;
#pragma unroll
    for (int c = 0; c < CPB; c++)
#pragma unroll
        for (int j = 0; j < 4; j++) {
            float2 v = unpack2(acc[c][j]);
            int n0 = 2 * j, n1 = 2 * j + 1;
            atomicAdd(ob + (((size_t)n0 * 32) + c) * HW, v.x);
            atomicAdd(ob + (((size_t)n1 * 32) + c) * HW, v.y);
        }
}

extern "C" void kernel_launch(void* const* d_in, const int* in_sizes, int n_in,
                              void* d_out, int out_size) {
    const float* x = (const float*)d_in[0];
    const float* wgt = (const float*)d_in[1];
    const float* bias = (const float*)d_in[2];
    float* out = (float*)d_out;

    build_xpad<<<(32 * 64 * 16 + 255) / 256, 256>>>(x);
    prep<<<(8 * 32 * HW / 4) / 256, 256>>>(bias, (float4*)out);
    dim3 grid(2, 16, 8 * SPLIT);                   // 2 x 16 x 32 = 1024 blocks
    dim3 block(32, 4);                             // 128 threads
    svconv_main<<<grid, block>>>(wgt, out);
}

// round 14
// speedup vs baseline: 1.0411x; 1.0251x over previous
#include <cuda_runtime.h>

// SVConv2d: out[n,o,h,w] = bias[o] + sum_{ci,kh,kw} x[n,ci,h+kh-1,w+kw-1] * W[o,ci,kh,kw,h,w]
// N=8, Cin=Cout=32, K=3, H=W=64. Weight (151 MB) streams once -> DRAM-bound.
// R14: single fused prep kernel (out=bias init + x transpose at 8x the
// thread parallelism + border zero) replacing two latency-bound kernels.
// Main: CPB=4, SPLIT=8 (2048 blocks, CINS=4) for a finer tail; burst-
// prefetched double-buffered weights; atomics epilogue.

typedef unsigned long long ull;

#define HW 4096
#define PD 66            // padded spatial dim
#define PP (PD * PD)     // 4356
#define SPLIT 8
#define CPB 4
#define CINS (32 / SPLIT)   // 4 cins per block

// scratch (allocation-free: __device__ globals)
__device__ float4 g_xp0[32 * PP];              // (cin, 66, 66) n0..3 : 2.2 MB
__device__ float4 g_xp1[32 * PP];              // (cin, 66, 66) n4..7 : 2.2 MB

__device__ __forceinline__ ull pack2(float a, float b) {
    ull r; asm("mov.b64 %0, {%1, %2};" : "=l"(r) : "f"(a), "f"(b)); return r;
}
__device__ __forceinline__ void fma2(ull& d, ull a, ull b) {
    asm("fma.rn.f32x2 %0, %1, %2, %0;" : "+l"(d) : "l"(a), "l"(b));
}
__device__ __forceinline__ float2 unpack2(ull v) {
    float x, y; asm("mov.b64 {%0, %1}, %2;" : "=f"(x), "=f"(y) : "l"(v));
    return make_float2(x, y);
}

// ---- kernel 1: fused prep ----
// Every thread: out-init (bias) + one transpose unit (1/8 of a (cin,h,w4) item).
// First 8320 threads also zero the padded border.
__global__ __launch_bounds__(256) void prep_all(const float* __restrict__ x,
                                                const float* __restrict__ bias,
                                                float4* __restrict__ out) {
    int idx = blockIdx.x * 256 + threadIdx.x;      // < 262144

    // (a) out = bias
    float b = __ldg(bias + ((idx >> 10) & 31));
    out[idx] = make_float4(b, b, b, b);

    // (b) transpose: item = (cin,h,w4), n = idx & 7  (262144 = 32768 items x 8)
    int item = idx >> 3, n = idx & 7;
    int cin = item >> 10;
    int rem = item & 1023;
    int h = rem >> 4;
    int w4 = (rem & 15) * 4;
    float4 v = *(const float4*)(x + (size_t)(n * 32 + cin) * HW + h * 64 + w4);
    float4* base = ((n < 4) ? g_xp0 : g_xp1) + (size_t)cin * PP + (h + 1) * PD + (w4 + 1);
    int comp = n & 3;
    ((float*)(base + 0))[comp] = v.x;
    ((float*)(base + 1))[comp] = v.y;
    ((float*)(base + 2))[comp] = v.z;
    ((float*)(base + 3))[comp] = v.w;

    // (c) border zero (260 cells per cin)
    if (idx < 32 * 260) {
        int bc = idx / 260, r = idx - bc * 260;
        int hp, wp;
        if (r < 66)       { hp = 0;            wp = r; }
        else if (r < 132) { hp = 65;           wp = r - 66; }
        else if (r < 196) { hp = r - 132 + 1;  wp = 0; }
        else              { hp = r - 196 + 1;  wp = 65; }
        float4 z = make_float4(0.f, 0.f, 0.f, 0.f);
        g_xp0[bc * PP + hp * PD + wp] = z;
        g_xp1[bc * PP + hp * PD + wp] = z;
    }
}

// load 36 weights (9 taps x 4 couts) for one cin into registers (one burst)
__device__ __forceinline__ void loadW(float* wb, const float* wp) {
#pragma unroll
    for (int c = 0; c < CPB; c++)
#pragma unroll
        for (int t = 0; t < 9; t++)
            wb[c * 9 + t] = __ldcs(wp + (size_t)c * (32 * 9 * HW) + t * HW);
}

// consume one cin: 18 x-load quads worth of FMAs with registered weights
__device__ __forceinline__ void fmaTaps(const float* wb,
                                        const float4* xb0, const float4* xb1,
                                        ull acc[CPB][4]) {
#pragma unroll
    for (int t = 0; t < 9; t++) {
        const int off = (t / 3 - 1) * PD + (t % 3 - 1);  // compile-time
        float4 lo = __ldg(xb0 + off);
        float4 hi = __ldg(xb1 + off);
        ull xq0 = pack2(lo.x, lo.y);
        ull xq1 = pack2(lo.z, lo.w);
        ull xq2 = pack2(hi.x, hi.y);
        ull xq3 = pack2(hi.z, hi.w);
#pragma unroll
        for (int c = 0; c < CPB; c++) {
            ull wd = pack2(wb[c * 9 + t], wb[c * 9 + t]);
            fma2(acc[c][0], wd, xq0);
            fma2(acc[c][1], wd, xq1);
            fma2(acc[c][2], wd, xq2);
            fma2(acc[c][3], wd, xq3);
        }
    }
}

// ---- kernel 2: main. block (32,4); warp = 32 consecutive w; no smem/barriers ----
__global__ __launch_bounds__(128) void svconv_main(const float* __restrict__ wt_g,
                                                   float* __restrict__ out) {
    const int lane = threadIdx.x, row = threadIdx.y;
    const int px = blockIdx.x * 32 + lane;
    const int py = blockIdx.y * 4 + row;
    const int c0 = (blockIdx.z & 7) * CPB;         // cout group (4 couts)
    const int s = blockIdx.z >> 3;                 // cin eighth

    ull acc[CPB][4];
#pragma unroll
    for (int c = 0; c < CPB; c++)
#pragma unroll
        for (int j = 0; j < 4; j++) acc[c][j] = 0ull;

    const float4* xb0 = g_xp0 + (size_t)(s * CINS) * PP + (py + 1) * PD + (px + 1);
    const float4* xb1 = g_xp1 + (size_t)(s * CINS) * PP + (py + 1) * PD + (px + 1);
    const float* wp = wt_g + (size_t)(c0 * 32 + s * CINS) * 9 * HW + py * 64 + px;

    float wA[36], wB[36];
    loadW(wA, wp);                                  // first cin

#pragma unroll 1
    for (int ci = 0; ci < CINS; ci += 2) {
        // prefetch cin+1 (burst), then consume cin
        loadW(wB, wp + (size_t)9 * HW);
        fmaTaps(wA, xb0, xb1, acc);
        xb0 += PP; xb1 += PP;

        // prefetch cin+2 (burst, clamped in-bounds on last), then consume cin+1
        const float* p2 = wp + (size_t)(ci + 2 < CINS ? 2 : 0) * 9 * HW;
        loadW(wA, p2);
        fmaTaps(wB, xb0, xb1, acc);
        xb0 += PP; xb1 += PP;

        wp += (size_t)18 * HW;                     // advance 2 cins
    }

    // ---- epilogue: atomic accumulate into out (bias pre-added by prep) ----
    float* ob = out + (size_t)c0 * HW + py * 64 + px;
#pragma unroll
    for (int c = 0; c < CPB; c++)
#pragma unroll
        for (int j = 0; j < 4; j++) {
            float2 v = unpack2(acc[c][j]);
            int n0 = 2 * j, n1 = 2 * j + 1;
            atomicAdd(ob + (((size_t)n0 * 32) + c) * HW, v.x);
            atomicAdd(ob + (((size_t)n1 * 32) + c) * HW, v.y);
        }
}

extern "C" void kernel_launch(void* const* d_in, const int* in_sizes, int n_in,
                              void* d_out, int out_size) {
    const float* x = (const float*)d_in[0];
    const float* wgt = (const float*)d_in[1];
    const float* bias = (const float*)d_in[2];
    float* out = (float*)d_out;

    prep_all<<<(8 * 32 * HW / 4) / 256, 256>>>(x, bias, (float4*)out);
    dim3 grid(2, 16, 8 * SPLIT);                   // 2 x 16 x 64 = 2048 blocks
    dim3 block(32, 4);                             // 128 threads
    svconv_main<<<grid, block>>>(wgt, out);
}

// round 15
// speedup vs baseline: 1.0629x; 1.0210x over previous
#include <cuda_runtime.h>

// SVConv2d: out[n,o,h,w] = bias[o] + sum_{ci,kh,kw} x[n,ci,h+kh-1,w+kw-1] * W[o,ci,kh,kw,h,w]
// N=8, Cin=Cout=32, K=3, H=W=64. Weight (151 MB) streams once -> DRAM-bound.
// R15: SPLIT=4 (CINS=8, 1024 blocks — R13 sweet spot) with the redundant
// clamped last-prefetch ELIMINATED by peeling the final iteration pair
// (saves 12.5% weight DRAM traffic vs R13, 25% vs R14). Fused prep kernel.
// CPB=4, burst-prefetched double-buffered weights, atomics epilogue.

typedef unsigned long long ull;

#define HW 4096
#define PD 66            // padded spatial dim
#define PP (PD * PD)     // 4356
#define SPLIT 4
#define CPB 4
#define CINS (32 / SPLIT)   // 8 cins per block

// scratch (allocation-free: __device__ globals)
__device__ float4 g_xp0[32 * PP];              // (cin, 66, 66) n0..3 : 2.2 MB
__device__ float4 g_xp1[32 * PP];              // (cin, 66, 66) n4..7 : 2.2 MB

__device__ __forceinline__ ull pack2(float a, float b) {
    ull r; asm("mov.b64 %0, {%1, %2};" : "=l"(r) : "f"(a), "f"(b)); return r;
}
__device__ __forceinline__ void fma2(ull& d, ull a, ull b) {
    asm("fma.rn.f32x2 %0, %1, %2, %0;" : "+l"(d) : "l"(a), "l"(b));
}
__device__ __forceinline__ float2 unpack2(ull v) {
    float x, y; asm("mov.b64 {%0, %1}, %2;" : "=f"(x), "=f"(y) : "l"(v));
    return make_float2(x, y);
}

// ---- kernel 1: fused prep ----
// Every thread: out-init (bias) + one transpose unit (1/8 of a (cin,h,w4) item).
// First 8320 threads also zero the padded border.
__global__ __launch_bounds__(256) void prep_all(const float* __restrict__ x,
                                                const float* __restrict__ bias,
                                                float4* __restrict__ out) {
    int idx = blockIdx.x * 256 + threadIdx.x;      // < 262144

    // (a) out = bias
    float b = __ldg(bias + ((idx >> 10) & 31));
    out[idx] = make_float4(b, b, b, b);

    // (b) transpose: item = (cin,h,w4), n = idx & 7  (262144 = 32768 items x 8)
    int item = idx >> 3, n = idx & 7;
    int cin = item >> 10;
    int rem = item & 1023;
    int h = rem >> 4;
    int w4 = (rem & 15) * 4;
    float4 v = *(const float4*)(x + (size_t)(n * 32 + cin) * HW + h * 64 + w4);
    float4* base = ((n < 4) ? g_xp0 : g_xp1) + (size_t)cin * PP + (h + 1) * PD + (w4 + 1);
    int comp = n & 3;
    ((float*)(base + 0))[comp] = v.x;
    ((float*)(base + 1))[comp] = v.y;
    ((float*)(base + 2))[comp] = v.z;
    ((float*)(base + 3))[comp] = v.w;

    // (c) border zero (260 cells per cin)
    if (idx < 32 * 260) {
        int bc = idx / 260, r = idx - bc * 260;
        int hp, wp;
        if (r < 66)       { hp = 0;            wp = r; }
        else if (r < 132) { hp = 65;           wp = r - 66; }
        else if (r < 196) { hp = r - 132 + 1;  wp = 0; }
        else              { hp = r - 196 + 1;  wp = 65; }
        float4 z = make_float4(0.f, 0.f, 0.f, 0.f);
        g_xp0[bc * PP + hp * PD + wp] = z;
        g_xp1[bc * PP + hp * PD + wp] = z;
    }
}

// load 36 weights (9 taps x 4 couts) for one cin into registers (one burst)
__device__ __forceinline__ void loadW(float* wb, const float* wp) {
#pragma unroll
    for (int c = 0; c < CPB; c++)
#pragma unroll
        for (int t = 0; t < 9; t++)
            wb[c * 9 + t] = __ldcs(wp + (size_t)c * (32 * 9 * HW) + t * HW);
}

// consume one cin: 18 x-load quads worth of FMAs with registered weights
__device__ __forceinline__ void fmaTaps(const float* wb,
                                        const float4* xb0, const float4* xb1,
                                        ull acc[CPB][4]) {
#pragma unroll
    for (int t = 0; t < 9; t++) {
        const int off = (t / 3 - 1) * PD + (t % 3 - 1);  // compile-time
        float4 lo = __ldg(xb0 + off);
        float4 hi = __ldg(xb1 + off);
        ull xq0 = pack2(lo.x, lo.y);
        ull xq1 = pack2(lo.z, lo.w);
        ull xq2 = pack2(hi.x, hi.y);
        ull xq3 = pack2(hi.z, hi.w);
#pragma unroll
        for (int c = 0; c < CPB; c++) {
            ull wd = pack2(wb[c * 9 + t], wb[c * 9 + t]);
            fma2(acc[c][0], wd, xq0);
            fma2(acc[c][1], wd, xq1);
            fma2(acc[c][2], wd, xq2);
            fma2(acc[c][3], wd, xq3);
        }
    }
}

// ---- kernel 2: main. block (32,4); warp = 32 consecutive w; no smem/barriers ----
__global__ __launch_bounds__(128) void svconv_main(const float* __restrict__ wt_g,
                                                   float* __restrict__ out) {
    const int lane = threadIdx.x, row = threadIdx.y;
    const int px = blockIdx.x * 32 + lane;
    const int py = blockIdx.y * 4 + row;
    const int c0 = (blockIdx.z & 7) * CPB;         // cout group (4 couts)
    const int s = blockIdx.z >> 3;                 // cin quarter

    ull acc[CPB][4];
#pragma unroll
    for (int c = 0; c < CPB; c++)
#pragma unroll
        for (int j = 0; j < 4; j++) acc[c][j] = 0ull;

    const float4* xb0 = g_xp0 + (size_t)(s * CINS) * PP + (py + 1) * PD + (px + 1);
    const float4* xb1 = g_xp1 + (size_t)(s * CINS) * PP + (py + 1) * PD + (px + 1);
    const float* wp = wt_g + (size_t)(c0 * 32 + s * CINS) * 9 * HW + py * 64 + px;

    float wA[36], wB[36];
    loadW(wA, wp);                                  // first cin

    // main loop over cins 0..CINS-3 (prefetching one cin ahead, no waste)
#pragma unroll 1
    for (int ci = 0; ci < CINS - 2; ci += 2) {
        loadW(wB, wp + (size_t)9 * HW);            // prefetch cin+1
        fmaTaps(wA, xb0, xb1, acc);                // consume cin
        xb0 += PP; xb1 += PP;

        loadW(wA, wp + (size_t)18 * HW);           // prefetch cin+2
        fmaTaps(wB, xb0, xb1, acc);                // consume cin+1
        xb0 += PP; xb1 += PP;

        wp += (size_t)18 * HW;                     // advance 2 cins
    }

    // peeled final pair: no redundant prefetch
    loadW(wB, wp + (size_t)9 * HW);                // prefetch last cin
    fmaTaps(wA, xb0, xb1, acc);                    // consume cin CINS-2
    xb0 += PP; xb1 += PP;
    fmaTaps(wB, xb0, xb1, acc);                    // consume cin CINS-1

    // ---- epilogue: atomic accumulate into out (bias pre-added by prep) ----
    float* ob = out + (size_t)c0 * HW + py * 64 + px;
#pragma unroll
    for (int c = 0; c < CPB; c++)
#pragma unroll
        for (int j = 0; j < 4; j++) {
            float2 v = unpack2(acc[c][j]);
            int n0 = 2 * j, n1 = 2 * j + 1;
            atomicAdd(ob + (((size_t)n0 * 32) + c) * HW, v.x);
            atomicAdd(ob + (((size_t)n1 * 32) + c) * HW, v.y);
        }
}

extern "C" void kernel_launch(void* const* d_in, const int* in_sizes, int n_in,
                              void* d_out, int out_size) {
    const float* x = (const float*)d_in[0];
    const float* wgt = (const float*)d_in[1];
    const float* bias = (const float*)d_in[2];
    float* out = (float*)d_out;

    prep_all<<<(8 * 32 * HW / 4) / 256, 256>>>(x, bias, (float4*)out);
    dim3 grid(2, 16, 8 * SPLIT);                   // 2 x 16 x 32 = 1024 blocks
    dim3 block(32, 4);                             // 128 threads
    svconv_main<<<grid, block>>>(wgt, out);
}